// round 10
// baseline (speedup 1.0000x reference)
#include <cuda_runtime.h>
#include <cuda_fp16.h>
#include <cstdint>
#include <cstddef>

// out = W[4096x128] @ Aug[128x16384] via mma.sync fp16.
// Persistent work-stealing GEMM: grid 296 (=2x148), 1024 tickets.

#define NCHUNK 16
#define BHTOT  1024
#define NCOLS  (NCHUNK * BHTOT)   // 16384

// ---------------- scratch (static device memory) --------------------------
__device__ float g_P64[4096];               // A^64
__device__ float g_Kvec[64 * 64];           // K_d = A^d B
__device__ float g_UT[(size_t)BHTOT * 1024];     // input transposed [bh][seq]
__device__ __align__(16) __half g_WH[64 * 8192];            // W fp16, per k 64x128
__device__ __align__(16) __half g_AugH[(size_t)NCOLS * 128];  // fp16(Aug)
__device__ unsigned int g_ticket;

// ---------------- helpers ----------------
__device__ __forceinline__ uint32_t smem_u32(const void* p) {
    uint32_t a;
    asm("{ .reg .u64 t; cvta.to.shared.u64 t, %1; cvt.u32.u64 %0, t; }"
        : "=r"(a) : "l"(p));
    return a;
}
__device__ __forceinline__ void ldsm4(uint32_t* r, uint32_t addr) {
    asm volatile("ldmatrix.sync.aligned.m8n8.x4.shared.b16 {%0,%1,%2,%3}, [%4];"
                 : "=r"(r[0]), "=r"(r[1]), "=r"(r[2]), "=r"(r[3]) : "r"(addr));
}
__device__ __forceinline__ void mma16816(float* d, const uint32_t* a,
                                         const uint32_t* b) {
    asm volatile(
        "mma.sync.aligned.m16n8k16.row.col.f32.f16.f16.f32 "
        "{%0,%1,%2,%3},{%4,%5,%6,%7},{%8,%9},{%0,%1,%2,%3};"
        : "+f"(d[0]), "+f"(d[1]), "+f"(d[2]), "+f"(d[3])
        : "r"(a[0]), "r"(a[1]), "r"(a[2]), "r"(a[3]), "r"(b[0]), "r"(b[1]));
}
__device__ __forceinline__ void cp16(uint32_t dst, const void* src) {
    asm volatile("cp.async.cg.shared.global [%0], [%1], 16;"
                 :: "r"(dst), "l"(src));
}
__device__ __forceinline__ void cp_commit() {
    asm volatile("cp.async.commit_group;" ::: "memory");
}
template <int N>
__device__ __forceinline__ void cp_wait_n() {
    asm volatile("cp.async.wait_group %0;" :: "n"(N) : "memory");
}

// ---------------- in-CTA 64x64 matmul (pitch 65), 512 threads -------------
__device__ __forceinline__ void mm64x(float* D, const float* Aa,
                                      const float* Bb, int tid) {
    const int rg = tid >> 4;     // 0..31, rows 2rg, 2rg+1
    const int cg = tid & 15;     // cols 4cg..4cg+3
    float acc[2][4];
#pragma unroll
    for (int r = 0; r < 2; r++)
#pragma unroll
        for (int c = 0; c < 4; c++) acc[r][c] = 0.0f;
#pragma unroll 8
    for (int q = 0; q < 64; q++) {
        float a0 = Aa[(rg * 2 + 0) * 65 + q];
        float a1 = Aa[(rg * 2 + 1) * 65 + q];
        float b0 = Bb[q * 65 + cg * 4 + 0];
        float b1 = Bb[q * 65 + cg * 4 + 1];
        float b2 = Bb[q * 65 + cg * 4 + 2];
        float b3 = Bb[q * 65 + cg * 4 + 3];
        acc[0][0] = fmaf(a0, b0, acc[0][0]); acc[0][1] = fmaf(a0, b1, acc[0][1]);
        acc[0][2] = fmaf(a0, b2, acc[0][2]); acc[0][3] = fmaf(a0, b3, acc[0][3]);
        acc[1][0] = fmaf(a1, b0, acc[1][0]); acc[1][1] = fmaf(a1, b1, acc[1][1]);
        acc[1][2] = fmaf(a1, b2, acc[1][2]); acc[1][3] = fmaf(a1, b3, acc[1][3]);
    }
#pragma unroll
    for (int r = 0; r < 2; r++)
#pragma unroll
        for (int c = 0; c < 4; c++)
            D[(rg * 2 + r) * 65 + cg * 4 + c] = acc[r][c];
    __syncthreads();
}

// ---------------- fused prep1: powers (blocks 0-63) + transpose (64-1087) -
// dynamic smem: 12544 floats (3x 64x65 buffers + 64) -- transpose reuses it.
__device__ void powers_body(const float* __restrict__ A,
                            const float* __restrict__ Bv,
                            float* sm, int c, int tid) {
    float* pw  = sm;
    float* res = sm + 4160;
    float* tmp = sm + 8320;
    float* bs  = sm + 12480;
    const int e = c + 1;          // 1..64

    for (int i = tid; i < 4096; i += 512)
        pw[(i >> 6) * 65 + (i & 63)] = A[i];
    if (tid < 64) bs[tid] = Bv[tid];
    __syncthreads();

    bool has = false;
    int rem = e;
    while (true) {
        if (rem & 1) {
            if (!has) {
                for (int i = tid; i < 4096; i += 512) {
                    int o = (i >> 6) * 65 + (i & 63);
                    res[o] = pw[o];
                }
                __syncthreads();
                has = true;
            } else {
                mm64x(tmp, res, pw, tid);
                float* t = res; res = tmp; tmp = t;
            }
        }
        rem >>= 1;
        if (!rem) break;
        mm64x(tmp, pw, pw, tid);
        float* t = pw; pw = tmp; tmp = t;
    }
    if (e == 64) {
        for (int i = tid; i < 4096; i += 512)
            g_P64[i] = res[(i >> 6) * 65 + (i & 63)];
    }
    for (int i = tid; i < 4096; i += 512) {
        int n = i >> 6, m = i & 63;
        g_WH[(size_t)c * 8192 + n * 128 + m] = __float2half(res[n * 65 + m]);
    }
    if (e <= 63) {
        if (tid < 64) {
            float a = 0.0f;
#pragma unroll 8
            for (int q = 0; q < 64; q++) a = fmaf(res[tid * 65 + q], bs[q], a);
            g_Kvec[e * 64 + tid] = a;
        }
    }
    if (c == 0 && tid < 64) g_Kvec[tid] = bs[tid];
}

__device__ void transpose_body(const float* __restrict__ inp,
                               float* sm, int idx, int tid) {
    float (*tile)[33] = reinterpret_cast<float(*)[33]>(sm);
    const int tx = tid & 31, ty = tid >> 5;          // 32 x 16
    const int t0 = (idx & 31) * 32;
    const int h0 = ((idx >> 5) & 7) * 32;
    const int b  = idx >> 8;
    const float* src = inp + (size_t)b * 1024 * 256;
#pragma unroll
    for (int i2 = 0; i2 < 2; i2++) {
        int row = ty + 16 * i2;
        tile[row][tx] = src[(size_t)(t0 + row) * 256 + h0 + tx];
    }
    __syncthreads();
    const int j = t0 >> 6;
    const int s0 = t0 & 63;
#pragma unroll
    for (int i2 = 0; i2 < 2; i2++) {
        int hr = ty + 16 * i2;
        int bh = b * 256 + h0 + hr;
        float v = tile[tx][hr];
        g_UT[(size_t)bh * 1024 + t0 + tx] = v;
        g_AugH[(size_t)(j * 1024 + bh) * 128 + 64 + s0 + tx] = __float2half(v);
    }
}

#define PREP1_SMEM (12544 * 4)

__global__ void __launch_bounds__(512) prep1_kernel(
    const float* __restrict__ A, const float* __restrict__ Bv,
    const float* __restrict__ inp) {
    extern __shared__ float psm[];
    const int tid = threadIdx.x;
    if (blockIdx.x == 0 && tid == 0) g_ticket = 0;   // reset work counter
    if (blockIdx.x < 64) powers_body(A, Bv, psm, blockIdx.x, tid);
    else                 transpose_body(inp, psm, blockIdx.x - 64, tid);
}

// ---------------- fused v + scan + Aug E-half + W K-half ------------------
__global__ void vscanw_kernel(const float* __restrict__ x0) {
    __shared__ float sK[4096];
    __shared__ float sP[64 * 65];
    __shared__ float su[8][64];
    __shared__ float sbuf[8][64];
    int tid = threadIdx.x;
    for (int i = tid; i < 4096; i += 256) {
        sK[i] = g_Kvec[i];
        sP[(i >> 6) * 65 + (i & 63)] = g_P64[i];
    }
    __syncthreads();

    // W K-half triangle: this CTA's 2048-element slice of 64x4096
    {
        int base_i = blockIdx.x * 2048;
        for (int ii = tid; ii < 2048; ii += 256) {
            int idx = base_i + ii;
            int k = idx >> 12, n = (idx >> 6) & 63, s = idx & 63;
            float val = (s <= k) ? sK[(k - s) * 64 + n] : 0.0f;
            g_WH[(size_t)k * 8192 + n * 128 + 64 + s] = __float2half(val);
        }
    }

    int w = tid >> 5, lane = tid & 31;
    int bh = blockIdx.x * 8 + w;
    const float* up = g_UT + (size_t)bh * 1024;
    float s0 = x0[(size_t)bh * 64 + lane];
    float s1 = x0[(size_t)bh * 64 + lane + 32];
    g_AugH[(size_t)bh * 128 + lane]      = __float2half(s0);
    g_AugH[(size_t)bh * 128 + lane + 32] = __float2half(s1);
#pragma unroll 1
    for (int j = 1; j < 16; j++) {
        su[w][lane]      = up[(j - 1) * 64 + lane];
        su[w][lane + 32] = up[(j - 1) * 64 + lane + 32];
        sbuf[w][lane]      = s0;
        sbuf[w][lane + 32] = s1;
        __syncwarp();
        float a0 = 0.0f, a1 = 0.0f;
#pragma unroll 8
        for (int s = 0; s < 64; s++) {
            float u = su[w][s];
            a0 = fmaf(sK[(63 - s) * 64 + lane], u, a0);
            a1 = fmaf(sK[(63 - s) * 64 + lane + 32], u, a1);
        }
#pragma unroll 8
        for (int q = 0; q < 64; q++) {
            float xq = sbuf[w][q];
            a0 = fmaf(sP[lane * 65 + q], xq, a0);
            a1 = fmaf(sP[(lane + 32) * 65 + q], xq, a1);
        }
        __syncwarp();
        s0 = a0; s1 = a1;
        g_AugH[(size_t)(j * 1024 + bh) * 128 + lane]      = __float2half(s0);
        g_AugH[(size_t)(j * 1024 + bh) * 128 + lane + 32] = __float2half(s1);
    }
}

// ---------------- persistent work-stealing mma.sync GEMM ------------------
// 296 CTAs (occ 2), 1024 tickets: tk -> T=tk>>3, nh=(tk>>2)&1, kq=tk&3.
// Ticket = 128 Aug cols x 2 k-blocks x 4 kg (quarter, STEPS=5+kq const).
// smem pitch 272 B: Aug rows 0-127; W buf0 rows 128-255; buf1 rows 256-383.
#define PITCH    272
#define GEMM_SMEM (384 * 272)    // 104448

__device__ __forceinline__ void load_w(uint32_t base, int tid, int kg, int nh,
                                       int buf, int steps) {
    const int qmax = 2 * steps;
    const __half* wsrc = g_WH + (size_t)(kg * 4 + nh * 2) * 64 * 128;  // 128 rows
    uint32_t dst0 = base + (128 + buf * 128) * PITCH;
    for (int i = tid; i < 2048; i += 512) {
        int row = i >> 4, q = i & 15;
        if (q < qmax)
            cp16(dst0 + row * PITCH + q * 16, wsrc + (size_t)row * 128 + q * 8);
    }
    cp_commit();
}

template <int STEPS>
__device__ __forceinline__ void gemm_iter(uint32_t aH, uint32_t wBase,
                                          float* __restrict__ out,
                                          int T, int nh, int kg, int kb,
                                          int ns, int wm, int lane) {
    const uint32_t bRow = (lane & 7) + ((lane >> 4) & 1) * 8;
    const uint32_t bOff = ((lane >> 3) & 1) * 16;
    const uint32_t wHa = wBase + (kb * 64 + ns * 32 + bRow) * PITCH + bOff;

    float acc[2][4][4];
#pragma unroll
    for (int mt = 0; mt < 2; mt++)
#pragma unroll
        for (int nt = 0; nt < 4; nt++)
#pragma unroll
            for (int r = 0; r < 4; r++) acc[mt][nt][r] = 0.0f;

#pragma unroll
    for (int s = 0; s < STEPS; s++) {
        uint32_t ah[2][4];
        ldsm4(ah[0], aH + s * 32);
        ldsm4(ah[1], aH + 16 * PITCH + s * 32);
        uint32_t wh[2][4];
        ldsm4(wh[0], wHa + s * 32);
        ldsm4(wh[1], wHa + 16 * PITCH + s * 32);
#pragma unroll
        for (int mt = 0; mt < 2; mt++)
#pragma unroll
            for (int nt = 0; nt < 4; nt++)
                mma16816(acc[mt][nt], ah[mt], &wh[nt >> 1][(nt & 1) * 2]);
    }

    const int j  = T >> 3;
    const int b  = (T >> 1) & 3;
    const int h0 = (T & 1) << 7;
    const int k  = kg * 4 + nh * 2 + kb;
    const int t  = j * 64 + k;
    const size_t rowBase = (size_t)(b * 1024 + t) * 16384;
    const int rbase = lane >> 2;
    const int ncol  = ns * 32 + (lane & 3) * 2;
#pragma unroll
    for (int mt = 0; mt < 2; mt++) {
        const int cl0 = wm * 32 + mt * 16 + rbase;
        float* p0 = out + rowBase + (size_t)(h0 + cl0) * 64 + ncol;
        float* p1 = p0 + 8 * 64;
#pragma unroll
        for (int nt = 0; nt < 4; nt++) {
            *reinterpret_cast<float2*>(p0 + nt * 8) =
                make_float2(acc[mt][nt][0], acc[mt][nt][1]);
            *reinterpret_cast<float2*>(p1 + nt * 8) =
                make_float2(acc[mt][nt][2], acc[mt][nt][3]);
        }
    }
}

template <int KQ>
__device__ __forceinline__ void do_quarter(uint32_t base, uint32_t aH, int tid,
                                           float* __restrict__ out,
                                           int T, int nh, int kb, int ns,
                                           int wm, int lane) {
    constexpr int STEPS = 5 + KQ;
#pragma unroll
    for (int i = 0; i < 4; i++) {
        const int kg = KQ * 4 + i;
        if (i < 3) {
            load_w(base, tid, kg + 1, nh, (i + 1) & 1, STEPS);
            cp_wait_n<1>();
        } else {
            cp_wait_n<0>();
        }
        __syncthreads();
        const uint32_t wBase = base + (128 + (i & 1) * 128) * PITCH;
        gemm_iter<STEPS>(aH, wBase, out, T, nh, kg, kb, ns, wm, lane);
        __syncthreads();
    }
}

__global__ void __launch_bounds__(512, 2) gemm_kernel(float* __restrict__ out) {
    extern __shared__ char smraw[];
    __shared__ unsigned s_tk;
    const uint32_t base = smem_u32(smraw);
    const int tid = threadIdx.x;
    const int wid = tid >> 5, lane = tid & 31;
    const int kb = wid & 1, ns = (wid >> 1) & 1, wm = wid >> 2;

    const uint32_t aRow = (lane & 7) + ((lane >> 3) & 1) * 8;
    const uint32_t aOff = ((lane >> 4) & 1) * 16;
    const uint32_t aH = base + (wm * 32 + aRow) * PITCH + aOff;

    int lastT = -1;
    for (;;) {
        __syncthreads();
        if (tid == 0) s_tk = atomicAdd(&g_ticket, 1u);
        __syncthreads();
        const unsigned tk = s_tk;
        if (tk >= 1024u) break;
        const int T  = tk >> 3;
        const int nh = (tk >> 2) & 1;
        const int kq = tk & 3;

        if (T != lastT) {
            const __half* asrc = g_AugH + (size_t)T * 128 * 128;
            for (int i = tid; i < 2048; i += 512) {
                int row = i >> 4, q = i & 15;
                cp16(base + row * PITCH + q * 16, asrc + (size_t)row * 128 + q * 8);
            }
            lastT = T;
        }
        load_w(base, tid, kq * 4, nh, 0, 5 + kq);   // commits Aug+W0 together

        switch (kq) {
        case 0: do_quarter<0>(base, aH, tid, out, T, nh, kb, ns, wm, lane); break;
        case 1: do_quarter<1>(base, aH, tid, out, T, nh, kb, ns, wm, lane); break;
        case 2: do_quarter<2>(base, aH, tid, out, T, nh, kb, ns, wm, lane); break;
        default: do_quarter<3>(base, aH, tid, out, T, nh, kb, ns, wm, lane); break;
        }
    }
}

// ---------------- launcher ----------------
extern "C" void kernel_launch(void* const* d_in, const int* in_sizes, int n_in,
                              void* d_out, int out_size) {
    const float* inp = (const float*)d_in[0];   // [4,1024,256]
    const float* A   = (const float*)d_in[1];   // [64,64]
    const float* Bv  = (const float*)d_in[2];   // [64]
    const float* x0  = (const float*)d_in[3];   // [4,256,64]
    float* out = (float*)d_out;

    cudaFuncSetAttribute(prep1_kernel,
                         cudaFuncAttributeMaxDynamicSharedMemorySize, PREP1_SMEM);
    prep1_kernel<<<1088, 512, PREP1_SMEM>>>(A, Bv, inp);    // 1
    vscanw_kernel<<<128, 256>>>(x0);                        // 2

    cudaFuncSetAttribute(gemm_kernel,
                         cudaFuncAttributeMaxDynamicSharedMemorySize, GEMM_SMEM);
    gemm_kernel<<<296, 512, GEMM_SMEM>>>(out);              // 3
}

// round 11
// speedup vs baseline: 1.1261x; 1.1261x over previous
#include <cuda_runtime.h>
#include <cuda_fp16.h>
#include <cstdint>
#include <cstddef>

// out = W[4096x128] @ Aug[128x16384] via mma.sync fp16.
// Persistent GEMM, weighted static schedule: 296 CTAs, 4096 (T,nh,kg) tickets.

#define NCHUNK 16
#define BHTOT  1024
#define NCOLS  (NCHUNK * BHTOT)   // 16384

// ---------------- scratch (static device memory) --------------------------
__device__ float g_P64[4096];               // A^64
__device__ float g_Kvec[64 * 64];           // K_d = A^d B
__device__ __align__(16) __half g_WH[64 * 8192];            // W fp16, per k 64x128
__device__ __align__(16) __half g_AugH[(size_t)NCOLS * 128];  // fp16(Aug)

// ---------------- helpers ----------------
__device__ __forceinline__ uint32_t smem_u32(const void* p) {
    uint32_t a;
    asm("{ .reg .u64 t; cvta.to.shared.u64 t, %1; cvt.u32.u64 %0, t; }"
        : "=r"(a) : "l"(p));
    return a;
}
__device__ __forceinline__ void ldsm4(uint32_t* r, uint32_t addr) {
    asm volatile("ldmatrix.sync.aligned.m8n8.x4.shared.b16 {%0,%1,%2,%3}, [%4];"
                 : "=r"(r[0]), "=r"(r[1]), "=r"(r[2]), "=r"(r[3]) : "r"(addr));
}
__device__ __forceinline__ void mma16816(float* d, const uint32_t* a,
                                         const uint32_t* b) {
    asm volatile(
        "mma.sync.aligned.m16n8k16.row.col.f32.f16.f16.f32 "
        "{%0,%1,%2,%3},{%4,%5,%6,%7},{%8,%9},{%0,%1,%2,%3};"
        : "+f"(d[0]), "+f"(d[1]), "+f"(d[2]), "+f"(d[3])
        : "r"(a[0]), "r"(a[1]), "r"(a[2]), "r"(a[3]), "r"(b[0]), "r"(b[1]));
}
__device__ __forceinline__ void cp16(uint32_t dst, const void* src) {
    asm volatile("cp.async.cg.shared.global [%0], [%1], 16;"
                 :: "r"(dst), "l"(src));
}
__device__ __forceinline__ void cp_commit() {
    asm volatile("cp.async.commit_group;" ::: "memory");
}
template <int N>
__device__ __forceinline__ void cp_wait_n() {
    asm volatile("cp.async.wait_group %0;" :: "n"(N) : "memory");
}

// ---------------- in-CTA 64x64 matmul (pitch 65), 256 threads -------------
__device__ __forceinline__ void mm64(float* D, const float* Aa,
                                     const float* Bb, int tid) {
    const int rg = tid >> 4;
    const int cg = tid & 15;
    float acc[4][4];
#pragma unroll
    for (int r = 0; r < 4; r++)
#pragma unroll
        for (int c = 0; c < 4; c++) acc[r][c] = 0.0f;
#pragma unroll 4
    for (int q = 0; q < 64; q++) {
        float a0 = Aa[(rg * 4 + 0) * 65 + q];
        float a1 = Aa[(rg * 4 + 1) * 65 + q];
        float a2 = Aa[(rg * 4 + 2) * 65 + q];
        float a3 = Aa[(rg * 4 + 3) * 65 + q];
        float b0 = Bb[q * 65 + cg * 4 + 0];
        float b1 = Bb[q * 65 + cg * 4 + 1];
        float b2 = Bb[q * 65 + cg * 4 + 2];
        float b3 = Bb[q * 65 + cg * 4 + 3];
        acc[0][0] = fmaf(a0, b0, acc[0][0]); acc[0][1] = fmaf(a0, b1, acc[0][1]);
        acc[0][2] = fmaf(a0, b2, acc[0][2]); acc[0][3] = fmaf(a0, b3, acc[0][3]);
        acc[1][0] = fmaf(a1, b0, acc[1][0]); acc[1][1] = fmaf(a1, b1, acc[1][1]);
        acc[1][2] = fmaf(a1, b2, acc[1][2]); acc[1][3] = fmaf(a1, b3, acc[1][3]);
        acc[2][0] = fmaf(a2, b0, acc[2][0]); acc[2][1] = fmaf(a2, b1, acc[2][1]);
        acc[2][2] = fmaf(a2, b2, acc[2][2]); acc[2][3] = fmaf(a2, b3, acc[2][3]);
        acc[3][0] = fmaf(a3, b0, acc[3][0]); acc[3][1] = fmaf(a3, b1, acc[3][1]);
        acc[3][2] = fmaf(a3, b2, acc[3][2]); acc[3][3] = fmaf(a3, b3, acc[3][3]);
    }
#pragma unroll
    for (int r = 0; r < 4; r++)
#pragma unroll
        for (int c = 0; c < 4; c++)
            D[(rg * 4 + r) * 65 + cg * 4 + c] = acc[r][c];
    __syncthreads();
}

// ---------------- powers: CTA c = A^{c+1} (square&multiply), K, W P-half --
__global__ void __launch_bounds__(256, 1) powers_kernel(
    const float* __restrict__ A, const float* __restrict__ Bv) {
    __shared__ float b0s[64 * 65];
    __shared__ float b1s[64 * 65];
    __shared__ float b2s[64 * 65];
    __shared__ float bs[64];
    float* pw  = b0s;
    float* res = b1s;
    float* tmp = b2s;
    const int c = blockIdx.x;     // 0..63
    const int e = c + 1;          // 1..64
    const int tid = threadIdx.x;

    for (int i = tid; i < 4096; i += 256)
        pw[(i >> 6) * 65 + (i & 63)] = A[i];
    if (tid < 64) bs[tid] = Bv[tid];
    __syncthreads();

    bool has = false;
    int rem = e;
    while (true) {
        if (rem & 1) {
            if (!has) {
                for (int i = tid; i < 4096; i += 256) {
                    int o = (i >> 6) * 65 + (i & 63);
                    res[o] = pw[o];
                }
                __syncthreads();
                has = true;
            } else {
                mm64(tmp, res, pw, tid);
                float* t = res; res = tmp; tmp = t;
            }
        }
        rem >>= 1;
        if (!rem) break;
        mm64(tmp, pw, pw, tid);
        float* t = pw; pw = tmp; tmp = t;
    }
    if (e == 64) {
        for (int i = tid; i < 4096; i += 256)
            g_P64[i] = res[(i >> 6) * 65 + (i & 63)];
    }
    for (int i = tid; i < 4096; i += 256) {
        int n = i >> 6, m = i & 63;
        g_WH[(size_t)c * 8192 + n * 128 + m] = __float2half(res[n * 65 + m]);
    }
    if (e <= 63) {
        for (int n = tid; n < 64; n += 256) {
            float a = 0.0f;
#pragma unroll 8
            for (int q = 0; q < 64; q++) a = fmaf(res[n * 65 + q], bs[q], a);
            g_Kvec[e * 64 + n] = a;
        }
    }
    if (c == 0 && tid < 64) g_Kvec[tid] = bs[tid];
}

// ---------------- fused u-stage + v + scan + Aug both halves + W K-half ---
// CTA = 8 bh (grid 128, 256 thr). dyn smem layout (floats):
//   su  @0      : 8 x 1032   (u block, padded stride)
//   sK  @8256   : 4096
//   sP  @12352  : 64 x 65
//   sbuf@16512  : 8 x 64
#define VS_SMEM (17024 * 4)

__global__ void __launch_bounds__(256) vscanw_kernel(
    const float* __restrict__ inp, const float* __restrict__ x0) {
    extern __shared__ float vs[];
    float* su   = vs;
    float* sK   = vs + 8256;
    float* sP   = vs + 12352;
    float* sbuf = vs + 16512;
    const int tid = threadIdx.x;
    const int bh0 = blockIdx.x * 8;
    const int b   = bh0 >> 8;
    const int h0  = bh0 & 255;

    // stage u block: su[hh][t] = inp[b][t][h0+hh]  (32B-sector coalesced)
    {
        const float* src = inp + (size_t)b * 1024 * 256 + h0;
        const int hh = tid & 7;
        const int tb = tid >> 3;       // 0..31
#pragma unroll 4
        for (int it = 0; it < 32; it++) {
            int t = it * 32 + tb;
            su[hh * 1032 + t] = src[(size_t)t * 256 + hh];
        }
    }
    for (int i = tid; i < 4096; i += 256) {
        sK[i] = g_Kvec[i];
        sP[(i >> 6) * 65 + (i & 63)] = g_P64[i];
    }
    __syncthreads();

    // Aug u-half (fp16, coalesced)
    for (int idx = tid; idx < 8192; idx += 256) {
        int j = idx >> 9, hh = (idx >> 6) & 7, s = idx & 63;
        g_AugH[(size_t)(j * 1024 + bh0 + hh) * 128 + 64 + s] =
            __float2half(su[hh * 1032 + j * 64 + s]);
    }

    // W K-half triangle: this CTA's 2048-element slice of 64x4096
    {
        int base_i = blockIdx.x * 2048;
        for (int ii = tid; ii < 2048; ii += 256) {
            int idx = base_i + ii;
            int k = idx >> 12, n = (idx >> 6) & 63, s = idx & 63;
            float val = (s <= k) ? sK[(k - s) * 64 + n] : 0.0f;
            g_WH[(size_t)k * 8192 + n * 128 + 64 + s] = __float2half(val);
        }
    }

    // boundary scan + Aug E-half
    const int w = tid >> 5, lane = tid & 31;
    const int bh = bh0 + w;
    float s0 = x0[(size_t)bh * 64 + lane];
    float s1 = x0[(size_t)bh * 64 + lane + 32];
    g_AugH[(size_t)bh * 128 + lane]      = __float2half(s0);
    g_AugH[(size_t)bh * 128 + lane + 32] = __float2half(s1);
#pragma unroll 1
    for (int j = 1; j < 16; j++) {
        sbuf[w * 64 + lane]      = s0;
        sbuf[w * 64 + lane + 32] = s1;
        __syncwarp();
        float a0 = 0.0f, a1 = 0.0f;
        const float* uj = su + w * 1032 + (j - 1) * 64;
#pragma unroll 8
        for (int s = 0; s < 64; s++) {
            float u = uj[s];
            a0 = fmaf(sK[(63 - s) * 64 + lane], u, a0);
            a1 = fmaf(sK[(63 - s) * 64 + lane + 32], u, a1);
        }
#pragma unroll 8
        for (int q = 0; q < 64; q++) {
            float xq = sbuf[w * 64 + q];
            a0 = fmaf(sP[lane * 65 + q], xq, a0);
            a1 = fmaf(sP[(lane + 32) * 65 + q], xq, a1);
        }
        __syncwarp();
        s0 = a0; s1 = a1;
        g_AugH[(size_t)(j * 1024 + bh) * 128 + lane]      = __float2half(s0);
        g_AugH[(size_t)(j * 1024 + bh) * 128 + lane + 32] = __float2half(s1);
    }
}

// ---------------- persistent mma.sync GEMM, weighted static schedule ------
// 296 CTAs, 4096 tickets q: T=q>>5, nh=(q>>4)&1, kg=q&15, steps=5+(kg>>2).
// Ticket weight = steps+3; per-CTA range from closed-form cumulative invert.
// smem pitch 272 B: Aug rows 0-127; W buf0 rows 128-255; buf1 rows 256-383.
#define PITCH    272
#define GEMM_SMEM (384 * 272)    // 104448
#define NGRID    296
#define WTOT     38912ull        // 256 groups x 152

__device__ __forceinline__ void load_w(uint32_t base, int tid, int kg, int nh,
                                       int buf, int steps) {
    const int qmax = 2 * steps;
    const __half* wsrc = g_WH + (size_t)(kg * 4 + nh * 2) * 64 * 128;  // 128 rows
    uint32_t dst0 = base + (128 + buf * 128) * PITCH;
    for (int i = tid; i < 2048; i += 512) {
        int row = i >> 4, q = i & 15;
        if (q < qmax)
            cp16(dst0 + row * PITCH + q * 16, wsrc + (size_t)row * 128 + q * 8);
    }
    cp_commit();
}

template <int STEPS>
__device__ __forceinline__ void gemm_iter(uint32_t aH, uint32_t wBase,
                                          float* __restrict__ out,
                                          int T, int nh, int kg, int kb,
                                          int ns, int wm, int lane) {
    const uint32_t bRow = (lane & 7) + ((lane >> 4) & 1) * 8;
    const uint32_t bOff = ((lane >> 3) & 1) * 16;
    const uint32_t wHa = wBase + (kb * 64 + ns * 32 + bRow) * PITCH + bOff;

    float acc[2][4][4];
#pragma unroll
    for (int mt = 0; mt < 2; mt++)
#pragma unroll
        for (int nt = 0; nt < 4; nt++)
#pragma unroll
            for (int r = 0; r < 4; r++) acc[mt][nt][r] = 0.0f;

#pragma unroll
    for (int s = 0; s < STEPS; s++) {
        uint32_t ah[2][4];
        ldsm4(ah[0], aH + s * 32);
        ldsm4(ah[1], aH + 16 * PITCH + s * 32);
        uint32_t wh[2][4];
        ldsm4(wh[0], wHa + s * 32);
        ldsm4(wh[1], wHa + 16 * PITCH + s * 32);
#pragma unroll
        for (int mt = 0; mt < 2; mt++)
#pragma unroll
            for (int nt = 0; nt < 4; nt++)
                mma16816(acc[mt][nt], ah[mt], &wh[nt >> 1][(nt & 1) * 2]);
    }

    const int j  = T >> 3;
    const int b  = (T >> 1) & 3;
    const int h0 = (T & 1) << 7;
    const int k  = kg * 4 + nh * 2 + kb;
    const int t  = j * 64 + k;
    const size_t rowBase = (size_t)(b * 1024 + t) * 16384;
    const int rbase = lane >> 2;
    const int ncol  = ns * 32 + (lane & 3) * 2;
#pragma unroll
    for (int mt = 0; mt < 2; mt++) {
        const int cl0 = wm * 32 + mt * 16 + rbase;
        float* p0 = out + rowBase + (size_t)(h0 + cl0) * 64 + ncol;
        float* p1 = p0 + 8 * 64;
#pragma unroll
        for (int nt = 0; nt < 4; nt++) {
            *reinterpret_cast<float2*>(p0 + nt * 8) =
                make_float2(acc[mt][nt][0], acc[mt][nt][1]);
            *reinterpret_cast<float2*>(p1 + nt * 8) =
                make_float2(acc[mt][nt][2], acc[mt][nt][3]);
        }
    }
}

// smallest q with C(q) >= s, where C(q) = 152*(q>>4) + P[q&15]
__device__ __forceinline__ int find_q(unsigned long long s) {
    const int P[16] = {0, 8, 16, 24, 32, 41, 50, 59, 68, 78, 88, 98,
                       108, 119, 130, 141};
    int blk = (int)(s / 152ull);
    int r = (int)(s - (unsigned long long)blk * 152ull);
    int j = 0;
#pragma unroll
    for (int k2 = 0; k2 < 16; k2++) j += (P[k2] < r) ? 1 : 0;
    return blk * 16 + j;
}

__global__ void __launch_bounds__(512, 2) gemm_kernel(float* __restrict__ out) {
    extern __shared__ char smraw[];
    const uint32_t base = smem_u32(smraw);
    const int tid = threadIdx.x;
    const int wid = tid >> 5, lane = tid & 31;
    const int kb = wid & 1, ns = (wid >> 1) & 1, wm = wid >> 2;

    const int lo = find_q((unsigned long long)blockIdx.x * WTOT / NGRID);
    const int hi = find_q((unsigned long long)(blockIdx.x + 1) * WTOT / NGRID);

    const uint32_t aRow = (lane & 7) + ((lane >> 3) & 1) * 8;
    const uint32_t aOff = ((lane >> 4) & 1) * 16;
    const uint32_t aH = base + (wm * 32 + aRow) * PITCH + aOff;

    int lastT = -1;
    int buf = 0;
    bool pending = false;
#pragma unroll 1
    for (int q = lo; q < hi; q++) {
        const int T = q >> 5, nh = (q >> 4) & 1, kg = q & 15;
        const int kq = kg >> 2;
        if (!pending) {
            if (T != lastT) {
                const __half* asrc = g_AugH + (size_t)T * 128 * 128;
                for (int i = tid; i < 2048; i += 512) {
                    int row = i >> 4, qq = i & 15;
                    cp16(base + row * PITCH + qq * 16,
                         asrc + (size_t)row * 128 + qq * 8);
                }
                lastT = T;
            }
            load_w(base, tid, kg, nh, buf, 5 + kq);
        }
        const bool pf = (q + 1 < hi) && ((q + 1) >> 5 == lastT);
        if (pf) {
            load_w(base, tid, (q + 1) & 15, ((q + 1) >> 4) & 1, buf ^ 1,
                   5 + (((q + 1) & 15) >> 2));
            cp_wait_n<1>();
        } else {
            cp_wait_n<0>();
        }
        __syncthreads();
        const uint32_t wBase = base + (128 + buf * 128) * PITCH;
        switch (kq) {
        case 0: gemm_iter<5>(aH, wBase, out, T, nh, kg, kb, ns, wm, lane); break;
        case 1: gemm_iter<6>(aH, wBase, out, T, nh, kg, kb, ns, wm, lane); break;
        case 2: gemm_iter<7>(aH, wBase, out, T, nh, kg, kb, ns, wm, lane); break;
        default: gemm_iter<8>(aH, wBase, out, T, nh, kg, kb, ns, wm, lane); break;
        }
        __syncthreads();
        buf ^= 1;
        pending = pf;
    }
}

// ---------------- launcher ----------------
extern "C" void kernel_launch(void* const* d_in, const int* in_sizes, int n_in,
                              void* d_out, int out_size) {
    const float* inp = (const float*)d_in[0];   // [4,1024,256]
    const float* A   = (const float*)d_in[1];   // [64,64]
    const float* Bv  = (const float*)d_in[2];   // [64]
    const float* x0  = (const float*)d_in[3];   // [4,256,64]
    float* out = (float*)d_out;

    powers_kernel<<<64, 256>>>(A, Bv);                      // 1

    cudaFuncSetAttribute(vscanw_kernel,
                         cudaFuncAttributeMaxDynamicSharedMemorySize, VS_SMEM);
    vscanw_kernel<<<128, 256, VS_SMEM>>>(inp, x0);          // 2

    cudaFuncSetAttribute(gemm_kernel,
                         cudaFuncAttributeMaxDynamicSharedMemorySize, GEMM_SMEM);
    gemm_kernel<<<NGRID, 512, GEMM_SMEM>>>(out);            // 3
}

// round 12
// speedup vs baseline: 1.3552x; 1.2034x over previous
#include <cuda_runtime.h>
#include <cuda_fp16.h>
#include <cuda_bf16.h>
#include <cstdint>
#include <cstddef>

// out = W[4096x128] @ Aug[128x16384] via mma.sync fp16.
// powers: tensor-core bf16x3 square-and-multiply chains.
// Persistent GEMM, weighted static schedule: 296 CTAs, 4096 (T,nh,kg) tickets.

#define NCHUNK 16
#define BHTOT  1024
#define NCOLS  (NCHUNK * BHTOT)   // 16384

// ---------------- scratch (static device memory) --------------------------
__device__ float g_P64[4096];               // A^64
__device__ float g_Kvec[64 * 64];           // K_d = A^d B
__device__ __align__(16) __half g_WH[64 * 8192];            // W fp16, per k 64x128
__device__ __align__(16) __half g_AugH[(size_t)NCOLS * 128];  // fp16(Aug)

// ---------------- helpers ----------------
__device__ __forceinline__ uint32_t smem_u32(const void* p) {
    uint32_t a;
    asm("{ .reg .u64 t; cvta.to.shared.u64 t, %1; cvt.u32.u64 %0, t; }"
        : "=r"(a) : "l"(p));
    return a;
}
__device__ __forceinline__ void ldsm4(uint32_t* r, uint32_t addr) {
    asm volatile("ldmatrix.sync.aligned.m8n8.x4.shared.b16 {%0,%1,%2,%3}, [%4];"
                 : "=r"(r[0]), "=r"(r[1]), "=r"(r[2]), "=r"(r[3]) : "r"(addr));
}
__device__ __forceinline__ void mma16816(float* d, const uint32_t* a,
                                         const uint32_t* b) {
    asm volatile(
        "mma.sync.aligned.m16n8k16.row.col.f32.f16.f16.f32 "
        "{%0,%1,%2,%3},{%4,%5,%6,%7},{%8,%9},{%0,%1,%2,%3};"
        : "+f"(d[0]), "+f"(d[1]), "+f"(d[2]), "+f"(d[3])
        : "r"(a[0]), "r"(a[1]), "r"(a[2]), "r"(a[3]), "r"(b[0]), "r"(b[1]));
}
__device__ __forceinline__ void mma16816bf(float* d, const uint32_t* a,
                                           const uint32_t* b) {
    asm volatile(
        "mma.sync.aligned.m16n8k16.row.col.f32.bf16.bf16.f32 "
        "{%0,%1,%2,%3},{%4,%5,%6,%7},{%8,%9},{%0,%1,%2,%3};"
        : "+f"(d[0]), "+f"(d[1]), "+f"(d[2]), "+f"(d[3])
        : "r"(a[0]), "r"(a[1]), "r"(a[2]), "r"(a[3]), "r"(b[0]), "r"(b[1]));
}
__device__ __forceinline__ void cp16(uint32_t dst, const void* src) {
    asm volatile("cp.async.cg.shared.global [%0], [%1], 16;"
                 :: "r"(dst), "l"(src));
}
__device__ __forceinline__ void cp_commit() {
    asm volatile("cp.async.commit_group;" ::: "memory");
}
template <int N>
__device__ __forceinline__ void cp_wait_n() {
    asm volatile("cp.async.wait_group %0;" :: "n"(N) : "memory");
}

// ---------------- tensor-core powers ---------------------------------------
// Each matrix kept as 4 bf16 smem buffers (64x72 elems each):
//   H_row @ +0, L_row @ +4608, H_trans @ +9216, L_trans @ +13824 (elements)
// Group: pw @ elem 0, res @ elem 18432. Byte pitch 144 (conflict-free ldsm).
#define TCP    72
#define BUFE   4608                 // elements per buffer
#define GRPE   (4 * BUFE)           // 18432 elements per matrix group
#define POW_SMEM (2 * GRPE * 2)     // 73728 bytes

__device__ __forceinline__ void pow_write(__nv_bfloat16* sm, int gD,
                                          int r, int c, float v) {
    __nv_bfloat16 hi = __float2bfloat16(v);
    __nv_bfloat16 lo = __float2bfloat16(v - __bfloat162float(hi));
    sm[gD + r * TCP + c]                = hi;
    sm[gD + BUFE + r * TCP + c]         = lo;
    sm[gD + 2 * BUFE + c * TCP + r]     = hi;
    sm[gD + 3 * BUFE + c * TCP + r]     = lo;
}

// D = srcA x srcB (3-term bf16), written to group gD (may alias sources)
__device__ __forceinline__ void mm_tc(__nv_bfloat16* sm, uint32_t smb,
                                      int tid, int gA, int gB, int gD) {
    const int lane = tid & 31, wid = tid >> 5;
    const int m0 = (wid >> 1) * 16;
    const int n0 = (wid & 1) * 32;
    const uint32_t aRow = (lane & 7) + ((lane >> 3) & 1) * 8;
    const uint32_t aOff = ((lane >> 4) & 1) * 16;
    const uint32_t bRow = (lane & 7) + ((lane >> 4) & 1) * 8;
    const uint32_t bOff = ((lane >> 3) & 1) * 16;
    const uint32_t aB  = smb + (uint32_t)gA * 2 + (m0 + aRow) * 144 + aOff;
    const uint32_t b0B = smb + (uint32_t)(gB + 2 * BUFE) * 2
                             + (n0 + bRow) * 144 + bOff;
    const uint32_t b1B = b0B + 16 * 144;

    float acc[4][4];
#pragma unroll
    for (int nt = 0; nt < 4; nt++)
#pragma unroll
        for (int r = 0; r < 4; r++) acc[nt][r] = 0.0f;

#pragma unroll
    for (int k = 0; k < 4; k++) {
        uint32_t ah[4], al[4], b0h[4], b0l[4], b1h[4], b1l[4];
        ldsm4(ah,  aB + k * 32);
        ldsm4(al,  aB + BUFE * 2 + k * 32);
        ldsm4(b0h, b0B + k * 32);
        ldsm4(b0l, b0B + BUFE * 2 + k * 32);
        ldsm4(b1h, b1B + k * 32);
        ldsm4(b1l, b1B + BUFE * 2 + k * 32);
        // hi*hi
        mma16816bf(acc[0], ah, &b0h[0]); mma16816bf(acc[1], ah, &b0h[2]);
        mma16816bf(acc[2], ah, &b1h[0]); mma16816bf(acc[3], ah, &b1h[2]);
        // hi*lo
        mma16816bf(acc[0], ah, &b0l[0]); mma16816bf(acc[1], ah, &b0l[2]);
        mma16816bf(acc[2], ah, &b1l[0]); mma16816bf(acc[3], ah, &b1l[2]);
        // lo*hi
        mma16816bf(acc[0], al, &b0h[0]); mma16816bf(acc[1], al, &b0h[2]);
        mma16816bf(acc[2], al, &b1h[0]); mma16816bf(acc[3], al, &b1h[2]);
    }
    __syncthreads();                       // all reads done
    const int r0 = m0 + (lane >> 2);
#pragma unroll
    for (int nt = 0; nt < 4; nt++) {
        const int c0 = n0 + nt * 8 + (lane & 3) * 2;
        pow_write(sm, gD, r0,     c0,     acc[nt][0]);
        pow_write(sm, gD, r0,     c0 + 1, acc[nt][1]);
        pow_write(sm, gD, r0 + 8, c0,     acc[nt][2]);
        pow_write(sm, gD, r0 + 8, c0 + 1, acc[nt][3]);
    }
    __syncthreads();                       // writes visible
}

__global__ void __launch_bounds__(256, 1) powers_kernel(
    const float* __restrict__ A, const float* __restrict__ Bv) {
    extern __shared__ __nv_bfloat16 sm[];
    __shared__ float bs[64];
    const uint32_t smb = smem_u32(sm);
    const int c = blockIdx.x;     // 0..63
    const int e = c + 1;          // 1..64
    const int tid = threadIdx.x;

    // init pw group from A (fp32 -> hi/lo, row + trans)
    for (int i = tid; i < 4096; i += 256) {
        int r = i >> 6, cc = i & 63;
        pow_write(sm, 0, r, cc, A[i]);
    }
    if (tid < 64) bs[tid] = Bv[tid];
    __syncthreads();

    bool has = false;
    int rem = e;
    while (true) {
        if (rem & 1) {
            if (!has) {
                for (int i = tid; i < GRPE; i += 256) sm[GRPE + i] = sm[i];
                __syncthreads();
                has = true;
            } else {
                mm_tc(sm, smb, tid, GRPE, 0, GRPE);   // res = res x pw
            }
        }
        rem >>= 1;
        if (!rem) break;
        mm_tc(sm, smb, tid, 0, 0, 0);                 // pw = pw x pw
    }

    // reconstruct fp32 P[e] = hi + lo (res group row-major)
    for (int i = tid; i < 4096; i += 256) {
        int n = i >> 6, m = i & 63;
        float v = __bfloat162float(sm[GRPE + n * TCP + m])
                + __bfloat162float(sm[GRPE + BUFE + n * TCP + m]);
        g_WH[(size_t)c * 8192 + n * 128 + m] = __float2half(v);
        if (e == 64) g_P64[i] = v;
    }
    if (e <= 63 && tid < 64) {
        float a = 0.0f;
#pragma unroll 8
        for (int q = 0; q < 64; q++) {
            float v = __bfloat162float(sm[GRPE + tid * TCP + q])
                    + __bfloat162float(sm[GRPE + BUFE + tid * TCP + q]);
            a = fmaf(v, bs[q], a);
        }
        g_Kvec[e * 64 + tid] = a;
    }
    if (c == 0 && tid < 64) g_Kvec[tid] = bs[tid];
}

// ---------------- fused u-stage + v + scan + Aug both halves + W K-half ---
#define VS_SMEM (17024 * 4)

__global__ void __launch_bounds__(256) vscanw_kernel(
    const float* __restrict__ inp, const float* __restrict__ x0) {
    extern __shared__ float vs[];
    float* su   = vs;
    float* sK   = vs + 8256;
    float* sP   = vs + 12352;
    float* sbuf = vs + 16512;
    const int tid = threadIdx.x;
    const int bh0 = blockIdx.x * 8;
    const int b   = bh0 >> 8;
    const int h0  = bh0 & 255;

    {
        const float* src = inp + (size_t)b * 1024 * 256 + h0;
        const int hh = tid & 7;
        const int tb = tid >> 3;
#pragma unroll 4
        for (int it = 0; it < 32; it++) {
            int t = it * 32 + tb;
            su[hh * 1032 + t] = src[(size_t)t * 256 + hh];
        }
    }
    for (int i = tid; i < 4096; i += 256) {
        sK[i] = g_Kvec[i];
        sP[(i >> 6) * 65 + (i & 63)] = g_P64[i];
    }
    __syncthreads();

    for (int idx = tid; idx < 8192; idx += 256) {
        int j = idx >> 9, hh = (idx >> 6) & 7, s = idx & 63;
        g_AugH[(size_t)(j * 1024 + bh0 + hh) * 128 + 64 + s] =
            __float2half(su[hh * 1032 + j * 64 + s]);
    }
    {
        int base_i = blockIdx.x * 2048;
        for (int ii = tid; ii < 2048; ii += 256) {
            int idx = base_i + ii;
            int k = idx >> 12, n = (idx >> 6) & 63, s = idx & 63;
            float val = (s <= k) ? sK[(k - s) * 64 + n] : 0.0f;
            g_WH[(size_t)k * 8192 + n * 128 + 64 + s] = __float2half(val);
        }
    }

    const int w = tid >> 5, lane = tid & 31;
    const int bh = bh0 + w;
    float s0 = x0[(size_t)bh * 64 + lane];
    float s1 = x0[(size_t)bh * 64 + lane + 32];
    g_AugH[(size_t)bh * 128 + lane]      = __float2half(s0);
    g_AugH[(size_t)bh * 128 + lane + 32] = __float2half(s1);
#pragma unroll 1
    for (int j = 1; j < 16; j++) {
        sbuf[w * 64 + lane]      = s0;
        sbuf[w * 64 + lane + 32] = s1;
        __syncwarp();
        float a0 = 0.0f, a1 = 0.0f;
        const float* uj = su + w * 1032 + (j - 1) * 64;
#pragma unroll 8
        for (int s = 0; s < 64; s++) {
            float u = uj[s];
            a0 = fmaf(sK[(63 - s) * 64 + lane], u, a0);
            a1 = fmaf(sK[(63 - s) * 64 + lane + 32], u, a1);
        }
#pragma unroll 8
        for (int q = 0; q < 64; q++) {
            float xq = sbuf[w * 64 + q];
            a0 = fmaf(sP[lane * 65 + q], xq, a0);
            a1 = fmaf(sP[(lane + 32) * 65 + q], xq, a1);
        }
        __syncwarp();
        s0 = a0; s1 = a1;
        g_AugH[(size_t)(j * 1024 + bh) * 128 + lane]      = __float2half(s0);
        g_AugH[(size_t)(j * 1024 + bh) * 128 + lane + 32] = __float2half(s1);
    }
}

// ---------------- persistent mma.sync GEMM, weighted static schedule ------
#define PITCH    272
#define GEMM_SMEM (384 * 272)    // 104448
#define NGRID    296
#define WTOT     38912ull        // 256 groups x 152

__device__ __forceinline__ void load_w(uint32_t base, int tid, int kg, int nh,
                                       int buf, int steps) {
    const int qmax = 2 * steps;
    const __half* wsrc = g_WH + (size_t)(kg * 4 + nh * 2) * 64 * 128;
    uint32_t dst0 = base + (128 + buf * 128) * PITCH;
    for (int i = tid; i < 2048; i += 512) {
        int row = i >> 4, q = i & 15;
        if (q < qmax)
            cp16(dst0 + row * PITCH + q * 16, wsrc + (size_t)row * 128 + q * 8);
    }
    cp_commit();
}

template <int STEPS>
__device__ __forceinline__ void gemm_iter(uint32_t aH, uint32_t wBase,
                                          float* __restrict__ out,
                                          int T, int nh, int kg, int kb,
                                          int ns, int wm, int lane) {
    const uint32_t bRow = (lane & 7) + ((lane >> 4) & 1) * 8;
    const uint32_t bOff = ((lane >> 3) & 1) * 16;
    const uint32_t wHa = wBase + (kb * 64 + ns * 32 + bRow) * PITCH + bOff;

    float acc[2][4][4];
#pragma unroll
    for (int mt = 0; mt < 2; mt++)
#pragma unroll
        for (int nt = 0; nt < 4; nt++)
#pragma unroll
            for (int r = 0; r < 4; r++) acc[mt][nt][r] = 0.0f;

#pragma unroll
    for (int s = 0; s < STEPS; s++) {
        uint32_t ah[2][4];
        ldsm4(ah[0], aH + s * 32);
        ldsm4(ah[1], aH + 16 * PITCH + s * 32);
        uint32_t wh[2][4];
        ldsm4(wh[0], wHa + s * 32);
        ldsm4(wh[1], wHa + 16 * PITCH + s * 32);
#pragma unroll
        for (int mt = 0; mt < 2; mt++)
#pragma unroll
            for (int nt = 0; nt < 4; nt++)
                mma16816(acc[mt][nt], ah[mt], &wh[nt >> 1][(nt & 1) * 2]);
    }

    const int j  = T >> 3;
    const int b  = (T >> 1) & 3;
    const int h0 = (T & 1) << 7;
    const int k  = kg * 4 + nh * 2 + kb;
    const int t  = j * 64 + k;
    const size_t rowBase = (size_t)(b * 1024 + t) * 16384;
    const int rbase = lane >> 2;
    const int ncol  = ns * 32 + (lane & 3) * 2;
#pragma unroll
    for (int mt = 0; mt < 2; mt++) {
        const int cl0 = wm * 32 + mt * 16 + rbase;
        float* p0 = out + rowBase + (size_t)(h0 + cl0) * 64 + ncol;
        float* p1 = p0 + 8 * 64;
#pragma unroll
        for (int nt = 0; nt < 4; nt++) {
            __stcs(reinterpret_cast<float2*>(p0 + nt * 8),
                   make_float2(acc[mt][nt][0], acc[mt][nt][1]));
            __stcs(reinterpret_cast<float2*>(p1 + nt * 8),
                   make_float2(acc[mt][nt][2], acc[mt][nt][3]));
        }
    }
}

// smallest q with C(q) >= s, where C(q) = 152*(q>>4) + P[q&15]
__device__ __forceinline__ int find_q(unsigned long long s) {
    const int P[16] = {0, 8, 16, 24, 32, 41, 50, 59, 68, 78, 88, 98,
                       108, 119, 130, 141};
    int blk = (int)(s / 152ull);
    int r = (int)(s - (unsigned long long)blk * 152ull);
    int j = 0;
#pragma unroll
    for (int k2 = 0; k2 < 16; k2++) j += (P[k2] < r) ? 1 : 0;
    return blk * 16 + j;
}

__global__ void __launch_bounds__(512, 2) gemm_kernel(float* __restrict__ out) {
    extern __shared__ char smraw[];
    const uint32_t base = smem_u32(smraw);
    const int tid = threadIdx.x;
    const int wid = tid >> 5, lane = tid & 31;
    const int kb = wid & 1, ns = (wid >> 1) & 1, wm = wid >> 2;

    const int lo = find_q((unsigned long long)blockIdx.x * WTOT / NGRID);
    const int hi = find_q((unsigned long long)(blockIdx.x + 1) * WTOT / NGRID);

    const uint32_t aRow = (lane & 7) + ((lane >> 3) & 1) * 8;
    const uint32_t aOff = ((lane >> 4) & 1) * 16;
    const uint32_t aH = base + (wm * 32 + aRow) * PITCH + aOff;

    int lastT = -1;
    int buf = 0;
    bool pending = false;
#pragma unroll 1
    for (int q = lo; q < hi; q++) {
        const int T = q >> 5, nh = (q >> 4) & 1, kg = q & 15;
        const int kq = kg >> 2;
        if (!pending) {
            if (T != lastT) {
                const __half* asrc = g_AugH + (size_t)T * 128 * 128;
                for (int i = tid; i < 2048; i += 512) {
                    int row = i >> 4, qq = i & 15;
                    cp16(base + row * PITCH + qq * 16,
                         asrc + (size_t)row * 128 + qq * 8);
                }
                lastT = T;
            }
            load_w(base, tid, kg, nh, buf, 5 + kq);
        }
        const bool pf = (q + 1 < hi) && ((q + 1) >> 5 == lastT);
        if (pf) {
            load_w(base, tid, (q + 1) & 15, ((q + 1) >> 4) & 1, buf ^ 1,
                   5 + (((q + 1) & 15) >> 2));
            cp_wait_n<1>();
        } else {
            cp_wait_n<0>();
        }
        __syncthreads();
        const uint32_t wBase = base + (128 + buf * 128) * PITCH;
        switch (kq) {
        case 0: gemm_iter<5>(aH, wBase, out, T, nh, kg, kb, ns, wm, lane); break;
        case 1: gemm_iter<6>(aH, wBase, out, T, nh, kg, kb, ns, wm, lane); break;
        case 2: gemm_iter<7>(aH, wBase, out, T, nh, kg, kb, ns, wm, lane); break;
        default: gemm_iter<8>(aH, wBase, out, T, nh, kg, kb, ns, wm, lane); break;
        }
        __syncthreads();
        buf ^= 1;
        pending = pf;
    }
}

// ---------------- launcher ----------------
extern "C" void kernel_launch(void* const* d_in, const int* in_sizes, int n_in,
                              void* d_out, int out_size) {
    const float* inp = (const float*)d_in[0];   // [4,1024,256]
    const float* A   = (const float*)d_in[1];   // [64,64]
    const float* Bv  = (const float*)d_in[2];   // [64]
    const float* x0  = (const float*)d_in[3];   // [4,256,64]
    float* out = (float*)d_out;

    cudaFuncSetAttribute(powers_kernel,
                         cudaFuncAttributeMaxDynamicSharedMemorySize, POW_SMEM);
    powers_kernel<<<64, 256, POW_SMEM>>>(A, Bv);            // 1

    cudaFuncSetAttribute(vscanw_kernel,
                         cudaFuncAttributeMaxDynamicSharedMemorySize, VS_SMEM);
    vscanw_kernel<<<128, 256, VS_SMEM>>>(inp, x0);          // 2

    cudaFuncSetAttribute(gemm_kernel,
                         cudaFuncAttributeMaxDynamicSharedMemorySize, GEMM_SMEM);
    gemm_kernel<<<NGRID, 512, GEMM_SMEM>>>(out);            // 3
}